// round 2
// baseline (speedup 1.0000x reference)
#include <cuda_runtime.h>
#include <math.h>

#define BATCH  4
#define SEQ    2048
#define DMODEL 768
#define NHEAD  12
#define HDIM   64
#define MTOT   (BATCH*SEQ)

// ---------------- scratch (static device globals; no allocs allowed) ----------------
__device__ float g_q[MTOT*DMODEL];
__device__ float g_k[MTOT*DMODEL];
__device__ float g_v[MTOT*DMODEL];
__device__ float g_att[MTOT*DMODEL];
__device__ unsigned char g_ctx[MTOT];
__device__ int g_is_byte;

// ---------------- is_context dtype detection ----------------
// For int32 / float32 arrays holding {0,1}/{0.0,1.0}, every byte at offset%4==1 is 0.
// For a 1-byte bool array, ~half of those positions are nonzero elements.
__global__ void detect_dtype_kernel(const unsigned char* __restrict__ p, int nbytes) {
    __shared__ int found;
    if (threadIdx.x == 0) found = 0;
    __syncthreads();
    int loc = 0;
    for (int i = threadIdx.x; i < nbytes; i += blockDim.x)
        if ((i & 3) == 1 && p[i] != 0) loc = 1;
    if (loc) atomicOr(&found, 1);
    __syncthreads();
    if (threadIdx.x == 0) g_is_byte = found;
}

__global__ void ctx_convert_kernel(const void* __restrict__ p, int n) {
    int i = blockIdx.x * blockDim.x + threadIdx.x;
    if (i >= n) return;
    int v;
    if (g_is_byte) v = ((const unsigned char*)p)[i];
    else           v = ((const int*)p)[i];   // nonzero test also correct for float32 1.0f bits
    g_ctx[i] = v ? 1 : 0;
}

// ---------------- SGEMM: C[M,768] = A[M,768] @ W[768,768]^T + bias ----------------
// BM=128, BN=64, BK=16, 256 threads, 8x4 micro-tile per thread.
__global__ __launch_bounds__(256) void sgemm_bias_kernel(
    const float* __restrict__ A, const float* __restrict__ W,
    const float* __restrict__ bias, float* __restrict__ C)
{
    const int BM = 128, BN = 64, BK = 16;
    __shared__ __align__(16) float As[BK][BM];
    __shared__ __align__(16) float Bs[BK][BN];

    int t  = threadIdx.x;
    int tx = t & 15;    // N direction (4 cols each)
    int ty = t >> 4;    // M direction (8 rows each)
    int m0 = blockIdx.y * BM;
    int n0 = blockIdx.x * BN;

    float acc[8][4];
#pragma unroll
    for (int i = 0; i < 8; i++)
#pragma unroll
        for (int j = 0; j < 4; j++) acc[i][j] = 0.f;

    const float* Aptr = A + (size_t)m0 * DMODEL;
    const float* Wptr = W + (size_t)n0 * DMODEL;

    for (int k0 = 0; k0 < DMODEL; k0 += BK) {
        // A tile: 128x16 = 512 float4, 2 per thread
#pragma unroll
        for (int u = 0; u < 2; u++) {
            int f = t + 256 * u;
            int row = f >> 2, c4 = f & 3;
            float4 a = *(const float4*)&Aptr[(size_t)row * DMODEL + k0 + c4 * 4];
            As[c4*4+0][row] = a.x; As[c4*4+1][row] = a.y;
            As[c4*4+2][row] = a.z; As[c4*4+3][row] = a.w;
        }
        // W tile: 64x16 = 256 float4, 1 per thread
        {
            int row = t >> 2, c4 = t & 3;
            float4 w = *(const float4*)&Wptr[(size_t)row * DMODEL + k0 + c4 * 4];
            Bs[c4*4+0][row] = w.x; Bs[c4*4+1][row] = w.y;
            Bs[c4*4+2][row] = w.z; Bs[c4*4+3][row] = w.w;
        }
        __syncthreads();

#pragma unroll
        for (int kk = 0; kk < BK; kk++) {
            float ar[8], br[4];
#pragma unroll
            for (int i = 0; i < 8; i++) ar[i] = As[kk][ty * 8 + i];
#pragma unroll
            for (int j = 0; j < 4; j++) br[j] = Bs[kk][tx * 4 + j];
#pragma unroll
            for (int i = 0; i < 8; i++)
#pragma unroll
                for (int j = 0; j < 4; j++) acc[i][j] += ar[i] * br[j];
        }
        __syncthreads();
    }

    // epilogue: add bias, write out (float4 per row)
    float4 bv = *(const float4*)&bias[n0 + tx * 4];
#pragma unroll
    for (int i = 0; i < 8; i++) {
        int r = m0 + ty * 8 + i;
        float4 o;
        o.x = acc[i][0] + bv.x; o.y = acc[i][1] + bv.y;
        o.z = acc[i][2] + bv.z; o.w = acc[i][3] + bv.w;
        *(float4*)&C[(size_t)r * DMODEL + n0 + tx * 4] = o;
    }
}

// ---------------- Attention ----------------
// grid (SEQ/64, NHEAD, BATCH), 256 threads.
// 4 lanes per query (quad within warp), 16 head-dims per lane.
// Online softmax; masked keys skipped AFTER the warp-uniform shfl reduction
// (skip semantics == reference's additive -1e30 mask: p underflows to 0,
// and every row has >=1 allowed key since context rows attend to themselves).
// NOTE: the shuffles MUST be executed by all 32 lanes unconditionally —
// putting them inside `if (allowed)` deadlocks the warp (round-1 bug).
__global__ __launch_bounds__(256) void attn_kernel() {
    const int BQ = 64, BKV = 32;
    __shared__ __align__(16) float Ks[BKV][HDIM];
    __shared__ __align__(16) float Vs[BKV][HDIM];
    __shared__ unsigned char cs[BKV];

    int b  = blockIdx.z;
    int h  = blockIdx.y;
    int qi = blockIdx.x * BQ + (threadIdx.x >> 2);
    int dg = threadIdx.x & 3;                 // dim group: 16 dims each

    size_t qoff = ((size_t)(b * SEQ + qi)) * DMODEL + h * HDIM + dg * 16;
    float qreg[16];
#pragma unroll
    for (int i = 0; i < 4; i++) {
        float4 tq = *(const float4*)&g_q[qoff + i * 4];
        qreg[i*4+0] = tq.x; qreg[i*4+1] = tq.y; qreg[i*4+2] = tq.z; qreg[i*4+3] = tq.w;
    }
    bool ctx_q = g_ctx[b * SEQ + qi] != 0;

    float m = -INFINITY, l = 0.f;
    float acc[16];
#pragma unroll
    for (int i = 0; i < 16; i++) acc[i] = 0.f;

    for (int k0 = 0; k0 < SEQ; k0 += BKV) {
        // load K/V tile: 32x64 floats each = 512 float4, 2 per thread per array
#pragma unroll
        for (int u = 0; u < 2; u++) {
            int f = threadIdx.x + 256 * u;
            int row = f >> 4, c4 = f & 15;
            size_t base = ((size_t)(b * SEQ + k0 + row)) * DMODEL + h * HDIM + c4 * 4;
            *(float4*)&Ks[row][c4 * 4] = *(const float4*)&g_k[base];
            *(float4*)&Vs[row][c4 * 4] = *(const float4*)&g_v[base];
        }
        if (threadIdx.x < BKV) cs[threadIdx.x] = g_ctx[b * SEQ + k0 + threadIdx.x];
        __syncthreads();

#pragma unroll 4
        for (int j = 0; j < BKV; j++) {
            // --- warp-uniform part: dot product + quad reduction (ALL lanes) ---
            const float* kr = &Ks[j][dg * 16];
            float s = 0.f;
#pragma unroll
            for (int i = 0; i < 16; i++) s += qreg[i] * kr[i];
            s += __shfl_xor_sync(0xffffffffu, s, 1);
            s += __shfl_xor_sync(0xffffffffu, s, 2);
            s *= 0.125f;  // 1/sqrt(64)

            // --- divergence-safe part: scalar math only, no warp sync ---
            bool allowed = (!ctx_q) || (cs[j] != 0);
            if (allowed) {
                if (s > m) {
                    float corr = __expf(m - s);   // exp(-inf)=0 on first hit: zeroes cleanly
                    m = s;
                    l *= corr;
#pragma unroll
                    for (int i = 0; i < 16; i++) acc[i] *= corr;
                }
                float p = __expf(s - m);
                l += p;
                const float* vr = &Vs[j][dg * 16];
#pragma unroll
                for (int i = 0; i < 16; i++) acc[i] += p * vr[i];
            }
        }
        __syncthreads();
    }

    float inv = 1.f / l;
    size_t ooff = ((size_t)(b * SEQ + qi)) * DMODEL + h * HDIM + dg * 16;
#pragma unroll
    for (int i = 0; i < 4; i++) {
        float4 o;
        o.x = acc[i*4+0] * inv; o.y = acc[i*4+1] * inv;
        o.z = acc[i*4+2] * inv; o.w = acc[i*4+3] * inv;
        *(float4*)&g_att[ooff + i * 4] = o;
    }
}

// ---------------- launch ----------------
extern "C" void kernel_launch(void* const* d_in, const int* in_sizes, int n_in,
                              void* d_out, int out_size) {
    const float* x   = (const float*)d_in[0];
    const void*  ctx = d_in[1];
    const float* Wq  = (const float*)d_in[2];
    const float* bq  = (const float*)d_in[3];
    const float* Wk  = (const float*)d_in[4];
    const float* bk  = (const float*)d_in[5];
    const float* Wv  = (const float*)d_in[6];
    const float* bv  = (const float*)d_in[7];
    const float* Wo  = (const float*)d_in[8];
    const float* bo  = (const float*)d_in[9];
    float* out = (float*)d_out;

    float *qb, *kb, *vb, *ab;
    cudaGetSymbolAddress((void**)&qb, g_q);
    cudaGetSymbolAddress((void**)&kb, g_k);
    cudaGetSymbolAddress((void**)&vb, g_v);
    cudaGetSymbolAddress((void**)&ab, g_att);

    detect_dtype_kernel<<<1, 1024>>>((const unsigned char*)ctx, MTOT);
    ctx_convert_kernel<<<(MTOT + 255) / 256, 256>>>(ctx, MTOT);

    dim3 gg(DMODEL / 64, MTOT / 128);  // (12, 64)
    sgemm_bias_kernel<<<gg, 256>>>(x, Wq, bq, qb);
    sgemm_bias_kernel<<<gg, 256>>>(x, Wk, bk, kb);
    sgemm_bias_kernel<<<gg, 256>>>(x, Wv, bv, vb);

    attn_kernel<<<dim3(SEQ / 64, NHEAD, BATCH), 256>>>();

    sgemm_bias_kernel<<<gg, 256>>>(ab, Wo, bo, out);
}

// round 3
// speedup vs baseline: 2.6584x; 2.6584x over previous
#include <cuda_runtime.h>
#include <math.h>

#define BATCH  4
#define SEQ    2048
#define DMODEL 768
#define NHEAD  12
#define HDIM   64
#define MTOT   (BATCH*SEQ)

// ---------------- scratch (static device globals; no allocs allowed) ----------------
__device__ float g_q[MTOT*DMODEL];
__device__ float g_k[MTOT*DMODEL];
__device__ float g_v[MTOT*DMODEL];
__device__ float g_att[MTOT*DMODEL];
__device__ unsigned char g_ctx[MTOT];
__device__ int g_is_byte;

// ---------------- is_context dtype detection ----------------
__global__ void detect_dtype_kernel(const unsigned char* __restrict__ p, int nbytes) {
    __shared__ int found;
    if (threadIdx.x == 0) found = 0;
    __syncthreads();
    int loc = 0;
    for (int i = threadIdx.x; i < nbytes; i += blockDim.x)
        if ((i & 3) == 1 && p[i] != 0) loc = 1;
    if (loc) atomicOr(&found, 1);
    __syncthreads();
    if (threadIdx.x == 0) g_is_byte = found;
}

__global__ void ctx_convert_kernel(const void* __restrict__ p, int n) {
    int i = blockIdx.x * blockDim.x + threadIdx.x;
    if (i >= n) return;
    int v;
    if (g_is_byte) v = ((const unsigned char*)p)[i];
    else           v = ((const int*)p)[i];
    g_ctx[i] = v ? 1 : 0;
}

// ---------------- fast exp on the FMA pipe (no MUFU) ----------------
// e^x for x <= 0. Range-reduce: x*log2(e) = i + f, e^x = 2^i * e^(f*ln2).
// Deg-6 Taylor on g = f*ln2 in [0, ln2]: rel err ~1.5e-5. Very negative x
// clamps to 2^-126 * poly ~ 1e-38 (numerically identical to the reference's
// additive -1e30 mask after softmax normalization).
__device__ __forceinline__ float fast_exp(float x) {
    float t = fmaxf(x * 1.4426950408889634f, -126.0f);
    float fi = floorf(t);
    float g  = (t - fi) * 0.6931471805599453f;
    float p;
    p = fmaf(g, 1.0f/720.0f, 1.0f/120.0f);
    p = fmaf(g, p, 1.0f/24.0f);
    p = fmaf(g, p, 1.0f/6.0f);
    p = fmaf(g, p, 0.5f);
    p = fmaf(g, p, 1.0f);
    p = fmaf(g, p, 1.0f);
    int e = (int)fi;
    float sc = __int_as_float((e + 127) << 23);
    return p * sc;
}

// ---------------- SGEMM: C[M,768] = A[M,768] @ W[768,768]^T + bias ----------------
// BM=128, BN=128, BK=16, 256 threads, 8x8 micro-tile per thread.
__global__ __launch_bounds__(256) void sgemm_bias_kernel(
    const float* __restrict__ A, const float* __restrict__ W,
    const float* __restrict__ bias, float* __restrict__ C)
{
    const int BK = 16;
    __shared__ __align__(16) float As[BK][128];
    __shared__ __align__(16) float Bs[BK][128];

    int t  = threadIdx.x;
    int tx = t & 15;    // N direction (8 cols each)
    int ty = t >> 4;    // M direction (8 rows each)
    int m0 = blockIdx.y * 128;
    int n0 = blockIdx.x * 128;

    float acc[8][8];
#pragma unroll
    for (int i = 0; i < 8; i++)
#pragma unroll
        for (int j = 0; j < 8; j++) acc[i][j] = 0.f;

    const float* Aptr = A + (size_t)m0 * DMODEL;
    const float* Wptr = W + (size_t)n0 * DMODEL;

    for (int k0 = 0; k0 < DMODEL; k0 += BK) {
        // A tile + W tile: each 128 rows x 16 cols = 512 float4, 2 per thread
#pragma unroll
        for (int u = 0; u < 2; u++) {
            int f = t + 256 * u;
            int row = f >> 2, c4 = f & 3;
            float4 a = *(const float4*)&Aptr[(size_t)row * DMODEL + k0 + c4 * 4];
            As[c4*4+0][row] = a.x; As[c4*4+1][row] = a.y;
            As[c4*4+2][row] = a.z; As[c4*4+3][row] = a.w;
            float4 w = *(const float4*)&Wptr[(size_t)row * DMODEL + k0 + c4 * 4];
            Bs[c4*4+0][row] = w.x; Bs[c4*4+1][row] = w.y;
            Bs[c4*4+2][row] = w.z; Bs[c4*4+3][row] = w.w;
        }
        __syncthreads();

#pragma unroll
        for (int kk = 0; kk < BK; kk++) {
            float ar[8], br[8];
            *(float4*)&ar[0] = *(const float4*)&As[kk][ty * 8 + 0];
            *(float4*)&ar[4] = *(const float4*)&As[kk][ty * 8 + 4];
            *(float4*)&br[0] = *(const float4*)&Bs[kk][tx * 8 + 0];
            *(float4*)&br[4] = *(const float4*)&Bs[kk][tx * 8 + 4];
#pragma unroll
            for (int i = 0; i < 8; i++)
#pragma unroll
                for (int j = 0; j < 8; j++) acc[i][j] += ar[i] * br[j];
        }
        __syncthreads();
    }

    float4 bv0 = *(const float4*)&bias[n0 + tx * 8 + 0];
    float4 bv1 = *(const float4*)&bias[n0 + tx * 8 + 4];
#pragma unroll
    for (int i = 0; i < 8; i++) {
        int r = m0 + ty * 8 + i;
        float4 o0, o1;
        o0.x = acc[i][0] + bv0.x; o0.y = acc[i][1] + bv0.y;
        o0.z = acc[i][2] + bv0.z; o0.w = acc[i][3] + bv0.w;
        o1.x = acc[i][4] + bv1.x; o1.y = acc[i][5] + bv1.y;
        o1.z = acc[i][6] + bv1.z; o1.w = acc[i][7] + bv1.w;
        *(float4*)&C[(size_t)r * DMODEL + n0 + tx * 8 + 0] = o0;
        *(float4*)&C[(size_t)r * DMODEL + n0 + tx * 8 + 4] = o1;
    }
}

// ---------------- Attention: 1 thread = 1 query (all 64 dims in regs) ----------------
// grid (SEQ/128, NHEAD, BATCH), 128 threads. All lanes of a warp process the
// SAME key j -> smem reads of Ks[j]/Vs[j] are broadcasts; no shuffles; exactly
// one exp per (q,k) pair, computed on the FMA pipe.
__global__ __launch_bounds__(128) void attn_kernel() {
    const int BQ = 128, BKV = 64;
    __shared__ __align__(16) float Ks[BKV][HDIM];
    __shared__ __align__(16) float Vs[BKV][HDIM];
    __shared__ unsigned char cs[BKV];

    int b  = blockIdx.z;
    int h  = blockIdx.y;
    int qi = blockIdx.x * BQ + threadIdx.x;

    // load query (scale folded in)
    float q[HDIM];
    {
        const float4* qp = (const float4*)&g_q[((size_t)(b * SEQ + qi)) * DMODEL + h * HDIM];
#pragma unroll
        for (int i = 0; i < 16; i++) {
            float4 v = qp[i];
            q[i*4+0] = v.x * 0.125f; q[i*4+1] = v.y * 0.125f;
            q[i*4+2] = v.z * 0.125f; q[i*4+3] = v.w * 0.125f;
        }
    }
    bool ctx_q = g_ctx[b * SEQ + qi] != 0;

    float m = -INFINITY, l = 0.f;
    float acc[HDIM];
#pragma unroll
    for (int i = 0; i < HDIM; i++) acc[i] = 0.f;

    for (int k0 = 0; k0 < SEQ; k0 += BKV) {
        // K/V tiles: 64 rows x 16 float4 = 1024 float4 each; 8 per thread per array
#pragma unroll
        for (int u = 0; u < 8; u++) {
            int f = threadIdx.x + 128 * u;
            int row = f >> 4, c4 = f & 15;
            size_t base = ((size_t)(b * SEQ + k0 + row)) * DMODEL + h * HDIM + c4 * 4;
            *(float4*)&Ks[row][c4 * 4] = *(const float4*)&g_k[base];
            *(float4*)&Vs[row][c4 * 4] = *(const float4*)&g_v[base];
        }
        if (threadIdx.x < BKV) cs[threadIdx.x] = g_ctx[b * SEQ + k0 + threadIdx.x];
        __syncthreads();

#pragma unroll 1
        for (int j = 0; j < BKV; j++) {
            const float4* kr = (const float4*)&Ks[j][0];
            float s0 = 0.f, s1 = 0.f, s2 = 0.f, s3 = 0.f;
#pragma unroll
            for (int i = 0; i < 4; i++) {
                float4 a = kr[i*4+0], bb = kr[i*4+1], c = kr[i*4+2], d = kr[i*4+3];
                s0 += q[i*16+ 0]*a.x + q[i*16+ 1]*a.y + q[i*16+ 2]*a.z + q[i*16+ 3]*a.w;
                s1 += q[i*16+ 4]*bb.x + q[i*16+ 5]*bb.y + q[i*16+ 6]*bb.z + q[i*16+ 7]*bb.w;
                s2 += q[i*16+ 8]*c.x + q[i*16+ 9]*c.y + q[i*16+10]*c.z + q[i*16+11]*c.w;
                s3 += q[i*16+12]*d.x + q[i*16+13]*d.y + q[i*16+14]*d.z + q[i*16+15]*d.w;
            }
            float s = (s0 + s1) + (s2 + s3);

            bool allowed = (!ctx_q) || (cs[j] != 0);
            if (!allowed) s = -1e30f;

            if (s > m) {                     // rare after warmup
                float corr = fast_exp(m - s); // exp(-inf)=0 on first hit
                m = s;
                l *= corr;
#pragma unroll
                for (int i = 0; i < HDIM; i++) acc[i] *= corr;
            }
            float p = fast_exp(s - m);
            l += p;
            const float4* vr = (const float4*)&Vs[j][0];
#pragma unroll
            for (int i = 0; i < 16; i++) {
                float4 v = vr[i];
                acc[i*4+0] += p * v.x; acc[i*4+1] += p * v.y;
                acc[i*4+2] += p * v.z; acc[i*4+3] += p * v.w;
            }
        }
        __syncthreads();
    }

    float inv = 1.f / l;
    float* op = &g_att[((size_t)(b * SEQ + qi)) * DMODEL + h * HDIM];
#pragma unroll
    for (int i = 0; i < 16; i++) {
        float4 o;
        o.x = acc[i*4+0] * inv; o.y = acc[i*4+1] * inv;
        o.z = acc[i*4+2] * inv; o.w = acc[i*4+3] * inv;
        *(float4*)&op[i * 4] = o;
    }
}

// ---------------- launch ----------------
extern "C" void kernel_launch(void* const* d_in, const int* in_sizes, int n_in,
                              void* d_out, int out_size) {
    const float* x   = (const float*)d_in[0];
    const void*  ctx = d_in[1];
    const float* Wq  = (const float*)d_in[2];
    const float* bq  = (const float*)d_in[3];
    const float* Wk  = (const float*)d_in[4];
    const float* bk  = (const float*)d_in[5];
    const float* Wv  = (const float*)d_in[6];
    const float* bv  = (const float*)d_in[7];
    const float* Wo  = (const float*)d_in[8];
    const float* bo  = (const float*)d_in[9];
    float* out = (float*)d_out;

    float *qb, *kb, *vb, *ab;
    cudaGetSymbolAddress((void**)&qb, g_q);
    cudaGetSymbolAddress((void**)&kb, g_k);
    cudaGetSymbolAddress((void**)&vb, g_v);
    cudaGetSymbolAddress((void**)&ab, g_att);

    detect_dtype_kernel<<<1, 1024>>>((const unsigned char*)ctx, MTOT);
    ctx_convert_kernel<<<(MTOT + 255) / 256, 256>>>(ctx, MTOT);

    dim3 gg(DMODEL / 128, MTOT / 128);  // (6, 64)
    sgemm_bias_kernel<<<gg, 256>>>(x, Wq, bq, qb);
    sgemm_bias_kernel<<<gg, 256>>>(x, Wk, bk, kb);
    sgemm_bias_kernel<<<gg, 256>>>(x, Wv, bv, vb);

    attn_kernel<<<dim3(SEQ / 128, NHEAD, BATCH), 128>>>();

    sgemm_bias_kernel<<<gg, 256>>>(ab, Wo, bo, out);
}

// round 4
// speedup vs baseline: 6.7263x; 2.5302x over previous
#include <cuda_runtime.h>
#include <math.h>
#include <stdint.h>

#define BATCH  4
#define SEQ    2048
#define DMODEL 768
#define NHEAD  12
#define HDIM   64
#define MTOT   (BATCH*SEQ)

// ---------------- scratch (static device globals; no allocs allowed) ----------------
__device__ float g_q[MTOT*DMODEL];
__device__ float g_k[MTOT*DMODEL];
__device__ float g_v[MTOT*DMODEL];
__device__ float g_att[MTOT*DMODEL];
__device__ unsigned char g_ctx[MTOT];
__device__ int g_is_byte;

// ---------------- is_context dtype detection ----------------
__global__ void detect_dtype_kernel(const unsigned char* __restrict__ p, int nbytes) {
    __shared__ int found;
    if (threadIdx.x == 0) found = 0;
    __syncthreads();
    int loc = 0;
    for (int i = threadIdx.x; i < nbytes; i += blockDim.x)
        if ((i & 3) == 1 && p[i] != 0) loc = 1;
    if (loc) atomicOr(&found, 1);
    __syncthreads();
    if (threadIdx.x == 0) g_is_byte = found;
}

__global__ void ctx_convert_kernel(const void* __restrict__ p, int n) {
    int i = blockIdx.x * blockDim.x + threadIdx.x;
    if (i >= n) return;
    int v;
    if (g_is_byte) v = ((const unsigned char*)p)[i];
    else           v = ((const int*)p)[i];
    g_ctx[i] = v ? 1 : 0;
}

// ---------------- tf32 helpers ----------------
__device__ __forceinline__ uint32_t to_tf32(float x) {
    uint32_t r;
    asm("cvt.rna.tf32.f32 %0, %1;" : "=r"(r) : "f"(x));
    return r;
}

// D = A(16x8, row) * B(8x8, col) + C   (tf32 -> fp32)
__device__ __forceinline__ void mma_tf32(float* d, const uint32_t* a, const uint32_t* b, const float* c) {
    asm volatile(
        "mma.sync.aligned.m16n8k8.row.col.f32.tf32.tf32.f32 "
        "{%0,%1,%2,%3}, {%4,%5,%6,%7}, {%8,%9}, {%10,%11,%12,%13};"
        : "=f"(d[0]), "=f"(d[1]), "=f"(d[2]), "=f"(d[3])
        : "r"(a[0]), "r"(a[1]), "r"(a[2]), "r"(a[3]),
          "r"(b[0]), "r"(b[1]),
          "f"(c[0]), "f"(c[1]), "f"(c[2]), "f"(c[3]));
}

// ---------------- tf32 tensor-core GEMM: C[M,768] = A[M,768] @ W[768,768]^T + bias ----------------
// CTA tile 128x128, BK=32, 256 threads = 8 warps in 4(M) x 2(N); warp tile 32x64.
__global__ __launch_bounds__(256) void gemm_tc_kernel(
    const float* __restrict__ A, const float* __restrict__ W,
    const float* __restrict__ bias, float* __restrict__ C)
{
    __shared__ uint32_t As[32][132];   // [k][m], tf32
    __shared__ uint32_t Bs[32][136];   // [k][n], tf32  (B[k][n] = W[n][k])

    int t    = threadIdx.x;
    int lane = t & 31;
    int warp = t >> 5;
    int g    = lane >> 2;   // group id (row part)
    int tq   = lane & 3;    // thread-in-group (col part)
    int wm   = (warp & 3) * 32;
    int wn   = (warp >> 2) * 64;
    int m0   = blockIdx.y * 128;
    int n0   = blockIdx.x * 128;

    float acc[2][8][4];
#pragma unroll
    for (int mt = 0; mt < 2; mt++)
#pragma unroll
        for (int nt = 0; nt < 8; nt++)
#pragma unroll
            for (int c = 0; c < 4; c++) acc[mt][nt][c] = 0.f;

    int r  = t & 127;          // row within tile (both A-m and W-n)
    int kg = (t >> 7) * 16;    // k sub-block

    for (int k0 = 0; k0 < DMODEL; k0 += 32) {
        // stage A (128 x 32) into As[k][m], tf32
#pragma unroll
        for (int u = 0; u < 4; u++) {
            float4 v = *(const float4*)&A[(size_t)(m0 + r) * DMODEL + k0 + kg + 4 * u];
            As[kg + 4*u + 0][r] = to_tf32(v.x);
            As[kg + 4*u + 1][r] = to_tf32(v.y);
            As[kg + 4*u + 2][r] = to_tf32(v.z);
            As[kg + 4*u + 3][r] = to_tf32(v.w);
        }
        // stage W (128 x 32) into Bs[k][n], tf32
#pragma unroll
        for (int u = 0; u < 4; u++) {
            float4 v = *(const float4*)&W[(size_t)(n0 + r) * DMODEL + k0 + kg + 4 * u];
            Bs[kg + 4*u + 0][r] = to_tf32(v.x);
            Bs[kg + 4*u + 1][r] = to_tf32(v.y);
            Bs[kg + 4*u + 2][r] = to_tf32(v.z);
            Bs[kg + 4*u + 3][r] = to_tf32(v.w);
        }
        __syncthreads();

#pragma unroll
        for (int kk = 0; kk < 4; kk++) {
            uint32_t af[2][4];
#pragma unroll
            for (int mt = 0; mt < 2; mt++) {
                int rb = wm + mt * 16;
                af[mt][0] = As[kk*8 + tq    ][rb + g    ];
                af[mt][1] = As[kk*8 + tq    ][rb + g + 8];
                af[mt][2] = As[kk*8 + tq + 4][rb + g    ];
                af[mt][3] = As[kk*8 + tq + 4][rb + g + 8];
            }
#pragma unroll
            for (int nt = 0; nt < 8; nt++) {
                uint32_t bf[2];
                bf[0] = Bs[kk*8 + tq    ][wn + nt*8 + g];
                bf[1] = Bs[kk*8 + tq + 4][wn + nt*8 + g];
                mma_tf32(acc[0][nt], af[0], bf, acc[0][nt]);
                mma_tf32(acc[1][nt], af[1], bf, acc[1][nt]);
            }
        }
        __syncthreads();
    }

    // epilogue
#pragma unroll
    for (int mt = 0; mt < 2; mt++) {
#pragma unroll
        for (int nt = 0; nt < 8; nt++) {
            int row = m0 + wm + mt * 16 + g;
            int col = n0 + wn + nt * 8 + 2 * tq;
            float b0 = bias[col], b1 = bias[col + 1];
            float2 o0 = make_float2(acc[mt][nt][0] + b0, acc[mt][nt][1] + b1);
            float2 o1 = make_float2(acc[mt][nt][2] + b0, acc[mt][nt][3] + b1);
            *(float2*)&C[(size_t)row * DMODEL + col]       = o0;
            *(float2*)&C[(size_t)(row + 8) * DMODEL + col] = o1;
        }
    }
}

// ---------------- Flash attention on tensor cores ----------------
// grid (SEQ/128, NHEAD, BATCH), 256 threads = 8 warps, warp owns 16 query rows.
// KV tile = 32 keys. S = Q K^T via mma (Q frags in regs), branchless additive
// -1e30 mask (== reference), online softmax, P -> smem -> PV via mma.
__global__ __launch_bounds__(256) void attn_tc_kernel() {
    __shared__ uint32_t Ks[32][68];        // [key][dim] tf32
    __shared__ uint32_t Vs[32][68];        // [key][dim] tf32
    __shared__ uint32_t Ps[8][16][36];     // per-warp P tile, tf32
    __shared__ float km[32];               // 0 or -1e30 per key

    int t    = threadIdx.x;
    int lane = t & 31;
    int w    = t >> 5;
    int g    = lane >> 2;
    int tq   = lane & 3;

    int b  = blockIdx.z;
    int h  = blockIdx.y;
    int q0 = blockIdx.x * 128;
    int qrow = q0 + w * 16;

    // Q fragments (scale folded), kept in regs for all 64 KV tiles
    uint32_t qa[8][4];
    {
        const float* qb = &g_q[(size_t)(b * SEQ + qrow) * DMODEL + h * HDIM];
#pragma unroll
        for (int ks = 0; ks < 8; ks++) {
            qa[ks][0] = to_tf32(qb[(size_t)g       * DMODEL + ks*8 + tq    ] * 0.125f);
            qa[ks][1] = to_tf32(qb[(size_t)(g + 8) * DMODEL + ks*8 + tq    ] * 0.125f);
            qa[ks][2] = to_tf32(qb[(size_t)g       * DMODEL + ks*8 + tq + 4] * 0.125f);
            qa[ks][3] = to_tf32(qb[(size_t)(g + 8) * DMODEL + ks*8 + tq + 4] * 0.125f);
        }
    }
    float rf0 = g_ctx[b * SEQ + qrow + g    ] ? 1.f : 0.f;   // context-row flags
    float rf1 = g_ctx[b * SEQ + qrow + g + 8] ? 1.f : 0.f;

    float o[8][4];
#pragma unroll
    for (int nt = 0; nt < 8; nt++)
#pragma unroll
        for (int c = 0; c < 4; c++) o[nt][c] = 0.f;
    float m0r = -1e30f, m1r = -1e30f, l0 = 0.f, l1 = 0.f;

    for (int k0 = 0; k0 < SEQ; k0 += 32) {
        __syncthreads();   // protect Ks/Vs reuse
        // stage K/V tile (32 x 64) as tf32
#pragma unroll
        for (int u = 0; u < 2; u++) {
            int f = t + 256 * u;            // 0..511 float4 slots
            int key = f >> 4, c4 = f & 15;
            size_t base = (size_t)(b * SEQ + k0 + key) * DMODEL + h * HDIM + c4 * 4;
            float4 kv = *(const float4*)&g_k[base];
            Ks[key][c4*4 + 0] = to_tf32(kv.x); Ks[key][c4*4 + 1] = to_tf32(kv.y);
            Ks[key][c4*4 + 2] = to_tf32(kv.z); Ks[key][c4*4 + 3] = to_tf32(kv.w);
            float4 vv = *(const float4*)&g_v[base];
            Vs[key][c4*4 + 0] = to_tf32(vv.x); Vs[key][c4*4 + 1] = to_tf32(vv.y);
            Vs[key][c4*4 + 2] = to_tf32(vv.z); Vs[key][c4*4 + 3] = to_tf32(vv.w);
        }
        if (t < 32) km[t] = g_ctx[b * SEQ + k0 + t] ? 0.f : -1e30f;
        __syncthreads();

        // ---- S = Q K^T (16 x 32) ----
        float sacc[4][4];
#pragma unroll
        for (int nt = 0; nt < 4; nt++)
#pragma unroll
            for (int c = 0; c < 4; c++) sacc[nt][c] = 0.f;
#pragma unroll
        for (int ks = 0; ks < 8; ks++) {
#pragma unroll
            for (int nt = 0; nt < 4; nt++) {
                uint32_t bf[2];
                bf[0] = Ks[nt*8 + g][ks*8 + tq    ];
                bf[1] = Ks[nt*8 + g][ks*8 + tq + 4];
                mma_tf32(sacc[nt], qa[ks], bf, sacc[nt]);
            }
        }

        // ---- mask (additive -1e30, branchless) ----
#pragma unroll
        for (int nt = 0; nt < 4; nt++) {
            int col = nt*8 + 2*tq;
            float k0m = km[col], k1m = km[col + 1];
            sacc[nt][0] = fmaf(rf0, k0m, sacc[nt][0]);
            sacc[nt][1] = fmaf(rf0, k1m, sacc[nt][1]);
            sacc[nt][2] = fmaf(rf1, k0m, sacc[nt][2]);
            sacc[nt][3] = fmaf(rf1, k1m, sacc[nt][3]);
        }

        // ---- online softmax ----
        float mx0 = -1e30f, mx1 = -1e30f;
#pragma unroll
        for (int nt = 0; nt < 4; nt++) {
            mx0 = fmaxf(mx0, fmaxf(sacc[nt][0], sacc[nt][1]));
            mx1 = fmaxf(mx1, fmaxf(sacc[nt][2], sacc[nt][3]));
        }
        mx0 = fmaxf(mx0, __shfl_xor_sync(0xffffffffu, mx0, 1));
        mx0 = fmaxf(mx0, __shfl_xor_sync(0xffffffffu, mx0, 2));
        mx1 = fmaxf(mx1, __shfl_xor_sync(0xffffffffu, mx1, 1));
        mx1 = fmaxf(mx1, __shfl_xor_sync(0xffffffffu, mx1, 2));

        float mn0 = fmaxf(m0r, mx0), mn1 = fmaxf(m1r, mx1);
        float corr0 = __expf(m0r - mn0), corr1 = __expf(m1r - mn1);
        m0r = mn0; m1r = mn1;

        float rs0 = 0.f, rs1 = 0.f;
        __syncwarp();
#pragma unroll
        for (int nt = 0; nt < 4; nt++) {
            int col = nt*8 + 2*tq;
            float p00 = __expf(sacc[nt][0] - mn0);
            float p01 = __expf(sacc[nt][1] - mn0);
            float p10 = __expf(sacc[nt][2] - mn1);
            float p11 = __expf(sacc[nt][3] - mn1);
            rs0 += p00 + p01; rs1 += p10 + p11;
            Ps[w][g    ][col    ] = to_tf32(p00);
            Ps[w][g    ][col + 1] = to_tf32(p01);
            Ps[w][g + 8][col    ] = to_tf32(p10);
            Ps[w][g + 8][col + 1] = to_tf32(p11);
        }
        rs0 += __shfl_xor_sync(0xffffffffu, rs0, 1);
        rs0 += __shfl_xor_sync(0xffffffffu, rs0, 2);
        rs1 += __shfl_xor_sync(0xffffffffu, rs1, 1);
        rs1 += __shfl_xor_sync(0xffffffffu, rs1, 2);
        l0 = l0 * corr0 + rs0;
        l1 = l1 * corr1 + rs1;

        // rescale O accumulators
#pragma unroll
        for (int nt = 0; nt < 8; nt++) {
            o[nt][0] *= corr0; o[nt][1] *= corr0;
            o[nt][2] *= corr1; o[nt][3] *= corr1;
        }
        __syncwarp();

        // ---- O += P V  (16 x 64, k=32) ----
#pragma unroll
        for (int ks = 0; ks < 4; ks++) {
            uint32_t ap[4];
            ap[0] = Ps[w][g    ][ks*8 + tq    ];
            ap[1] = Ps[w][g + 8][ks*8 + tq    ];
            ap[2] = Ps[w][g    ][ks*8 + tq + 4];
            ap[3] = Ps[w][g + 8][ks*8 + tq + 4];
#pragma unroll
            for (int nt = 0; nt < 8; nt++) {
                uint32_t bf[2];
                bf[0] = Vs[ks*8 + tq    ][nt*8 + g];
                bf[1] = Vs[ks*8 + tq + 4][nt*8 + g];
                mma_tf32(o[nt], ap, bf, o[nt]);
            }
        }
    }

    // ---- normalize + write ----
    float inv0 = 1.f / l0, inv1 = 1.f / l1;
    float* ob = &g_att[(size_t)(b * SEQ + qrow) * DMODEL + h * HDIM];
#pragma unroll
    for (int nt = 0; nt < 8; nt++) {
        int col = nt*8 + 2*tq;
        *(float2*)&ob[(size_t)g       * DMODEL + col] = make_float2(o[nt][0] * inv0, o[nt][1] * inv0);
        *(float2*)&ob[(size_t)(g + 8) * DMODEL + col] = make_float2(o[nt][2] * inv1, o[nt][3] * inv1);
    }
}

// ---------------- launch ----------------
extern "C" void kernel_launch(void* const* d_in, const int* in_sizes, int n_in,
                              void* d_out, int out_size) {
    const float* x   = (const float*)d_in[0];
    const void*  ctx = d_in[1];
    const float* Wq  = (const float*)d_in[2];
    const float* bq  = (const float*)d_in[3];
    const float* Wk  = (const float*)d_in[4];
    const float* bk  = (const float*)d_in[5];
    const float* Wv  = (const float*)d_in[6];
    const float* bv  = (const float*)d_in[7];
    const float* Wo  = (const float*)d_in[8];
    const float* bo  = (const float*)d_in[9];
    float* out = (float*)d_out;

    float *qb, *kb, *vb, *ab;
    cudaGetSymbolAddress((void**)&qb, g_q);
    cudaGetSymbolAddress((void**)&kb, g_k);
    cudaGetSymbolAddress((void**)&vb, g_v);
    cudaGetSymbolAddress((void**)&ab, g_att);

    detect_dtype_kernel<<<1, 1024>>>((const unsigned char*)ctx, MTOT);
    ctx_convert_kernel<<<(MTOT + 255) / 256, 256>>>(ctx, MTOT);

    dim3 gg(DMODEL / 128, MTOT / 128);  // (6, 64)
    gemm_tc_kernel<<<gg, 256>>>(x, Wq, bq, qb);
    gemm_tc_kernel<<<gg, 256>>>(x, Wk, bk, kb);
    gemm_tc_kernel<<<gg, 256>>>(x, Wv, bv, vb);

    attn_tc_kernel<<<dim3(SEQ / 128, NHEAD, BATCH), 256>>>();

    gemm_tc_kernel<<<gg, 256>>>(ab, Wo, bo, out);
}